// round 6
// baseline (speedup 1.0000x reference)
#include <cuda_runtime.h>
#include <math.h>

#define EPS 1e-8f

// R5 winner structure + 256-bit global loads (sm_100+ ld.global.v8.b32).
// One warp = 8 rows; 4 lanes per row; each lane owns 16 contiguous columns
// loaded as 2 x 256-bit (instead of 4 x 128-bit) -> half the LDG count and
// half the L1tex wavefronts.
__device__ __forceinline__ void ldg256(const float* __restrict__ p, float r[8]) {
    unsigned u0, u1, u2, u3, u4, u5, u6, u7;
    asm("ld.global.v8.b32 {%0,%1,%2,%3,%4,%5,%6,%7}, [%8];"
        : "=r"(u0), "=r"(u1), "=r"(u2), "=r"(u3),
          "=r"(u4), "=r"(u5), "=r"(u6), "=r"(u7)
        : "l"(p));
    r[0] = __uint_as_float(u0); r[1] = __uint_as_float(u1);
    r[2] = __uint_as_float(u2); r[3] = __uint_as_float(u3);
    r[4] = __uint_as_float(u4); r[5] = __uint_as_float(u5);
    r[6] = __uint_as_float(u6); r[7] = __uint_as_float(u7);
}

__global__ void __launch_bounds__(256) hybrid_rbf_kernel(
    const float* __restrict__ x,
    const float* __restrict__ y,
    float* __restrict__ out,
    int B)
{
    const int warp_id = (blockIdx.x * blockDim.x + threadIdx.x) >> 5;
    const int lane    = threadIdx.x & 31;
    const int group   = lane >> 2;   // 0..7 : which row within the warp
    const int j       = lane & 3;    // 0..3 : 16-column slice within the row
    const int row     = warp_id * 8 + group;
    if (row >= B) return;

    const float* __restrict__ xp = x + (size_t)row * 64 + j * 16;
    const float* __restrict__ yp = y + (size_t)row * 64 + j * 16;

    // Issue all 4 x 256-bit loads up front (MLP = 4, same bytes as before)
    float xa[16], ya[16];
    ldg256(xp,     xa);
    ldg256(xp + 8, xa + 8);
    ldg256(yp,     ya);
    ldg256(yp + 8, ya + 8);

    // Fused single-pass moments: Sx, Sxx, Sy, Syy, Sxy
    float sx = 0.f, sxx = 0.f, sy = 0.f, syy = 0.f, sxy = 0.f;
    #pragma unroll
    for (int e = 0; e < 16; e++) {
        const float xv = xa[e], yv = ya[e];
        sx  += xv;
        sy  += yv;
        sxx = fmaf(xv, xv, sxx);
        syy = fmaf(yv, yv, syy);
        sxy = fmaf(xv, yv, sxy);
    }

    // Quantum term (predicated: only the 8 j==0 lanes run the MUFUs),
    // hoisted before the shuffles so the load registers retire early.
    float q = 0.f;
    if (j == 0) {
        q = __cosf(xa[0] - ya[0]) * __cosf(xa[1] - ya[1])
          * __cosf(xa[2] - ya[2]) * __cosf(xa[3] - ya[3])
          * __cosf(xa[4] - ya[4]) * __cosf(xa[5] - ya[5])
          * __cosf(xa[6] - ya[6]) * __cosf(xa[7] - ya[7]);
    }

    // Segmented butterfly reduction over the aligned 4-lane group
    #pragma unroll
    for (int o = 1; o <= 2; o <<= 1) {
        sx  += __shfl_xor_sync(0xFFFFFFFFu, sx,  o);
        sy  += __shfl_xor_sync(0xFFFFFFFFu, sy,  o);
        sxx += __shfl_xor_sync(0xFFFFFFFFu, sxx, o);
        syy += __shfl_xor_sync(0xFFFFFFFFu, syy, o);
        sxy += __shfl_xor_sync(0xFFFFFFFFu, sxy, o);
    }

    if (j == 0) {
        const float inv_n   = 1.0f / 64.0f;
        const float inv_nm1 = 1.0f / 63.0f;
        const float mx = sx * inv_n;
        const float my = sy * inv_n;
        const float vx = fmaxf((sxx - 64.0f * mx * mx) * inv_nm1, 0.0f);
        const float vy = fmaxf((syy - 64.0f * my * my) * inv_nm1, 0.0f);
        const float fx = 1.0f / (sqrtf(vx) + EPS);
        const float fy = 1.0f / (sqrtf(vy) + EPS);
        const float cov = sxy - 64.0f * mx * my;     // sum (x-mx)(y-my)
        // sum (xhat - yhat)^2 = 63*vx*fx^2 + 63*vy*fy^2 - 2*cov*fx*fy
        const float ss = 63.0f * vx * fx * fx
                       + 63.0f * vy * fy * fy
                       - 2.0f * cov * fx * fy;

        out[row] = __expf(-ss) + q * q;
    }
}

extern "C" void kernel_launch(void* const* d_in, const int* in_sizes, int n_in,
                              void* d_out, int out_size)
{
    const float* x = (const float*)d_in[0];
    const float* y = (const float*)d_in[1];
    float* out = (float*)d_out;
    const int B = in_sizes[0] / 64;

    const int threads = 256;                    // 8 warps -> 64 rows per block
    const int rows_per_block = (threads / 32) * 8;
    const int blocks = (B + rows_per_block - 1) / rows_per_block;
    hybrid_rbf_kernel<<<blocks, threads>>>(x, y, out, B);
}